// round 4
// baseline (speedup 1.0000x reference)
#include <cuda_runtime.h>

#define NN   50000
#define NHE  10000
#define NE   800000
#define NI   800000
#define HID  128
#define OUTC 64

// ---------------- device scratch (no allocations; referenced only in device code) ----------------
__device__ __align__(16) float g_A[NN * HID];    // theta-product / edge agg
__device__ __align__(16) float g_B[NN * HID];    // lin-product / agg@wrel
__device__ __align__(16) float g_X1[NN * HID];
__device__ __align__(16) float g_X2[NN * HID];
__device__ __align__(16) float g_M[NHE * HID];   // hyperedge features
__device__ __align__(16) float g_Wc[HID * HID];  // combined root+lin weight
__device__ __align__(16) float g_bsum[HID];      // combined bias
__device__ float g_Binv[NHE];
__device__ float g_Dinv[NN];

__device__ int g_idx64;          // 1 if index tensors are int64, 0 if int32
__device__ int g_deg_he[NHE];
__device__ int g_off_he[NHE + 1];
__device__ int g_cur_he[NHE];
__device__ int g_deg_nh[NN];
__device__ int g_off_nh[NN + 1];
__device__ int g_cur_nh[NN];
__device__ int g_deg_nd[NN];
__device__ int g_off_nd[NN + 1];
__device__ int g_cur_nd[NN];
__device__ int g_list_he[NI];   // nodes per hyperedge
__device__ int g_list_nh[NI];   // hyperedges per node
__device__ int g_list_nd[NE];   // srcs per dst node

__device__ __forceinline__ float leakyf(float x) { return x >= 0.f ? x : 0.01f * x; }
__device__ __forceinline__ int clampi(int v, int hi) { return v < 0 ? 0 : (v >= hi ? hi - 1 : v); }

// dtype-agnostic index read: pos is the logical element position in a [2, n] array.
// int64 case: little-endian low word at word-offset 2*pos (values < 2^31 so low word == value).
__device__ __forceinline__ int idxat(const int* __restrict__ a, int pos) {
    return g_idx64 ? a[2 * (long long)pos] : a[pos];
}

// buffer selectors: resolve device-global scratch inside device code (no host symbol APIs)
__device__ __forceinline__ const float* srcbuf(int id, const float* ext) {
    switch (id) {
        case 0: return g_A;
        case 1: return g_B;
        case 2: return g_X1;
        case 3: return g_X2;
        default: return ext;
    }
}
__device__ __forceinline__ float* dstbuf(int id, float* ext) {
    switch (id) {
        case 0: return g_A;
        case 1: return g_B;
        case 2: return g_X1;
        case 3: return g_X2;
        default: return ext;
    }
}

// ---------------- index dtype detect ----------------
// If tensors are int64 (values < 2^32, nonneg), every odd 32-bit word of the buffer is 0.
// If int32, odd words are random indices — essentially never all zero across 256 probes.
__global__ void detect_kernel(const int* __restrict__ he) {
    __shared__ int any;
    if (threadIdx.x == 0) any = 0;
    __syncthreads();
    if (he[2 * threadIdx.x + 1] != 0) atomicOr(&any, 1);
    __syncthreads();
    if (threadIdx.x == 0) g_idx64 = (any == 0) ? 1 : 0;
}

// ---------------- CSR build ----------------
__global__ void zero_deg_kernel() {
    int i = blockIdx.x * blockDim.x + threadIdx.x;
    if (i < NHE) g_deg_he[i] = 0;
    if (i < NN) { g_deg_nh[i] = 0; g_deg_nd[i] = 0; }
}

__global__ void count_kernel(const int* __restrict__ he, const int* __restrict__ ed) {
    int i = blockIdx.x * blockDim.x + threadIdx.x;
    if (i < NI) {
        atomicAdd(&g_deg_nh[clampi(idxat(he, i), NN)], 1);
        atomicAdd(&g_deg_he[clampi(idxat(he, NI + i), NHE)], 1);
    }
    if (i < NE) {
        atomicAdd(&g_deg_nd[clampi(idxat(ed, NE + i), NN)], 1);
    }
}

// single-block exclusive scan; which: 0=he, 1=node-hyper, 2=node-dst
__global__ void scan_kernel(int which) {
    const int* deg; int n; int* off; int* cur; float* inv;
    if (which == 0)      { deg = g_deg_he; n = NHE; off = g_off_he; cur = g_cur_he; inv = g_Binv; }
    else if (which == 1) { deg = g_deg_nh; n = NN;  off = g_off_nh; cur = g_cur_nh; inv = g_Dinv; }
    else                 { deg = g_deg_nd; n = NN;  off = g_off_nd; cur = g_cur_nd; inv = 0; }

    __shared__ int sh[1024];
    int tid = threadIdx.x;
    int chunk = (n + 1023) / 1024;
    int lo = tid * chunk;
    int hi = lo + chunk; if (hi > n) hi = n; if (lo > n) lo = n;
    int s = 0;
    for (int i = lo; i < hi; ++i) s += deg[i];
    sh[tid] = s;
    __syncthreads();
    for (int d = 1; d < 1024; d <<= 1) {
        int v = (tid >= d) ? sh[tid - d] : 0;
        __syncthreads();
        sh[tid] += v;
        __syncthreads();
    }
    int run = sh[tid] - s;  // exclusive prefix at chunk start
    for (int i = lo; i < hi; ++i) {
        int d = deg[i];
        off[i] = run; cur[i] = run;
        if (inv) inv[i] = d ? 1.0f / (float)d : 0.0f;
        run += d;
    }
    if (tid == 1023) off[n] = sh[1023];
}

__global__ void fill_kernel(const int* __restrict__ he, const int* __restrict__ ed) {
    int i = blockIdx.x * blockDim.x + threadIdx.x;
    if (i < NI) {
        int n = clampi(idxat(he, i), NN);
        int h = clampi(idxat(he, NI + i), NHE);
        g_list_he[atomicAdd(&g_cur_he[h], 1)] = n;
        g_list_nh[atomicAdd(&g_cur_nh[n], 1)] = h;
    }
    if (i < NE) {
        int s = clampi(idxat(ed, i), NN);
        int d = clampi(idxat(ed, NE + i), NN);
        g_list_nd[atomicAdd(&g_cur_nd[d], 1)] = s;
    }
}

// ---------------- gather segment-sums (1 warp per output row) ----------------
// node(theta-product in g_A) -> hyperedge (g_M), scaled by Binv
__global__ void gather_he_kernel() {
    int row = (blockIdx.x * blockDim.x + threadIdx.x) >> 5;
    if (row >= NHE) return;
    int lane = threadIdx.x & 31;
    int beg = g_off_he[row], end = g_off_he[row + 1];
    const float4* src = (const float4*)g_A;
    float ax = 0.f, ay = 0.f, az = 0.f, aw = 0.f;
    int i = beg;
    for (; i + 4 <= end; i += 4) {
        int n0 = g_list_he[i], n1 = g_list_he[i + 1], n2 = g_list_he[i + 2], n3 = g_list_he[i + 3];
        float4 v0 = src[n0 * 32 + lane];
        float4 v1 = src[n1 * 32 + lane];
        float4 v2 = src[n2 * 32 + lane];
        float4 v3 = src[n3 * 32 + lane];
        ax += (v0.x + v1.x) + (v2.x + v3.x);
        ay += (v0.y + v1.y) + (v2.y + v3.y);
        az += (v0.z + v1.z) + (v2.z + v3.z);
        aw += (v0.w + v1.w) + (v2.w + v3.w);
    }
    for (; i < end; ++i) {
        int n = g_list_he[i];
        float4 v = src[n * 32 + lane];
        ax += v.x; ay += v.y; az += v.z; aw += v.w;
    }
    float b = g_Binv[row];
    ((float4*)g_M)[row * 32 + lane] = make_float4(ax * b, ay * b, az * b, aw * b);
}

// hyperedge(g_M) -> node + Dinv scale + hc bias + lin branch(g_B) + lin bias + leaky (fused)
// outsel: 2 -> g_X1, 3 -> g_X2
__global__ void gather_node_fuse_kernel(const float4* __restrict__ hcb,
                                        const float4* __restrict__ linb,
                                        int outsel) {
    int row = (blockIdx.x * blockDim.x + threadIdx.x) >> 5;
    if (row >= NN) return;
    int lane = threadIdx.x & 31;
    int beg = g_off_nh[row], end = g_off_nh[row + 1];
    const float4* m = (const float4*)g_M;
    float ax = 0.f, ay = 0.f, az = 0.f, aw = 0.f;
    int i = beg;
    for (; i + 4 <= end; i += 4) {
        int h0 = g_list_nh[i], h1 = g_list_nh[i + 1], h2 = g_list_nh[i + 2], h3 = g_list_nh[i + 3];
        float4 v0 = m[h0 * 32 + lane];
        float4 v1 = m[h1 * 32 + lane];
        float4 v2 = m[h2 * 32 + lane];
        float4 v3 = m[h3 * 32 + lane];
        ax += (v0.x + v1.x) + (v2.x + v3.x);
        ay += (v0.y + v1.y) + (v2.y + v3.y);
        az += (v0.z + v1.z) + (v2.z + v3.z);
        aw += (v0.w + v1.w) + (v2.w + v3.w);
    }
    for (; i < end; ++i) {
        int h = g_list_nh[i];
        float4 v = m[h * 32 + lane];
        ax += v.x; ay += v.y; az += v.z; aw += v.w;
    }
    float dinv = g_Dinv[row];
    float4 b1 = hcb[lane];
    float4 b2 = linb[lane];
    const float4* linP = (const float4*)g_B;
    float4 l = linP[row * 32 + lane];
    float4 r;
    r.x = leakyf(ax * dinv + b1.x + b2.x + l.x);
    r.y = leakyf(ay * dinv + b1.y + b2.y + l.y);
    r.z = leakyf(az * dinv + b1.z + b2.z + l.z);
    r.w = leakyf(aw * dinv + b1.w + b2.w + l.w);
    ((float4*)dstbuf(outsel, 0))[row * 32 + lane] = r;
}

// neighbor sum over graph edges: src (g_X1 or g_X2) -> g_A
__global__ void gather_edge_kernel(int srcsel) {
    int row = (blockIdx.x * blockDim.x + threadIdx.x) >> 5;
    if (row >= NN) return;
    int lane = threadIdx.x & 31;
    int beg = g_off_nd[row], end = g_off_nd[row + 1];
    const float4* src = (const float4*)srcbuf(srcsel, 0);
    float ax = 0.f, ay = 0.f, az = 0.f, aw = 0.f;
    int i = beg;
    for (; i + 4 <= end; i += 4) {
        int n0 = g_list_nd[i], n1 = g_list_nd[i + 1], n2 = g_list_nd[i + 2], n3 = g_list_nd[i + 3];
        float4 v0 = src[n0 * 32 + lane];
        float4 v1 = src[n1 * 32 + lane];
        float4 v2 = src[n2 * 32 + lane];
        float4 v3 = src[n3 * 32 + lane];
        ax += (v0.x + v1.x) + (v2.x + v3.x);
        ay += (v0.y + v1.y) + (v2.y + v3.y);
        az += (v0.z + v1.z) + (v2.z + v3.z);
        aw += (v0.w + v1.w) + (v2.w + v3.w);
    }
    for (; i < end; ++i) {
        int n = g_list_nd[i];
        float4 v = src[n * 32 + lane];
        ax += v.x; ay += v.y; az += v.z; aw += v.w;
    }
    ((float4*)g_A)[row * 32 + lane] = make_float4(ax, ay, az, aw);
}

// weight/bias combine: Wc = a + b ; bsum = ba + bb
__global__ void combine_kernel(const float* __restrict__ a, const float* __restrict__ b,
                               const float* __restrict__ ba, const float* __restrict__ bb) {
    int i = blockIdx.x * blockDim.x + threadIdx.x;
    if (i < HID * HID) g_Wc[i] = a[i] + b[i];
    if (i < HID) g_bsum[i] = ba[i] + bb[i];
}

// ---------------- fp32 SGEMM: C[M x Kout] = A[M x 128] @ W[128 x Kout] ----------------
// MODE 0: C = acc ; MODE 1: C = acc + bias_ext ; MODE 2: C = leaky(acc + g_B + g_bsum)
// asel/csel: -1 = external pointer, else scratch id. wsel: 0 = ext, 1 = g_Wc.
template <int MODE>
__global__ void gemm_kernel(const float* __restrict__ Aext, const float* __restrict__ Wext,
                            float* __restrict__ Cext, const float* __restrict__ bias_ext,
                            int asel, int csel, int wsel, int M, int Kout) {
    const float* A = srcbuf(asel, Aext);
    const float* W = (wsel == 1) ? g_Wc : Wext;
    float* C = dstbuf(csel, Cext);

    __shared__ float As[64][68];  // [m][kk], padded
    __shared__ float Ws[64][64];  // [kk][n]
    int tid = threadIdx.x;
    int tx = tid & 15, ty = tid >> 4;
    int brow = blockIdx.y * 64;
    int bcol = blockIdx.x * 64;

    float acc[4][4];
#pragma unroll
    for (int i = 0; i < 4; ++i)
#pragma unroll
        for (int j = 0; j < 4; ++j) acc[i][j] = 0.f;

    for (int ks = 0; ks < 128; ks += 64) {
#pragma unroll
        for (int p = 0; p < 4; ++p) {
            int r  = (tid >> 4) + p * 16;
            int k4 = (tid & 15);
            int gr = brow + r;
            float4 v = make_float4(0.f, 0.f, 0.f, 0.f);
            if (gr < M) v = *(const float4*)&A[gr * 128 + ks + k4 * 4];
            As[r][k4 * 4 + 0] = v.x;
            As[r][k4 * 4 + 1] = v.y;
            As[r][k4 * 4 + 2] = v.z;
            As[r][k4 * 4 + 3] = v.w;
        }
#pragma unroll
        for (int p = 0; p < 4; ++p) {
            int kk = (tid >> 4) + p * 16;
            int n4 = (tid & 15);
            float4 v = *(const float4*)&W[(ks + kk) * Kout + bcol + n4 * 4];
            *(float4*)&Ws[kk][n4 * 4] = v;
        }
        __syncthreads();
#pragma unroll 8
        for (int kk = 0; kk < 64; ++kk) {
            float a0 = As[ty * 4 + 0][kk];
            float a1 = As[ty * 4 + 1][kk];
            float a2 = As[ty * 4 + 2][kk];
            float a3 = As[ty * 4 + 3][kk];
            float4 w = *(const float4*)&Ws[kk][tx * 4];
            acc[0][0] += a0 * w.x; acc[0][1] += a0 * w.y; acc[0][2] += a0 * w.z; acc[0][3] += a0 * w.w;
            acc[1][0] += a1 * w.x; acc[1][1] += a1 * w.y; acc[1][2] += a1 * w.z; acc[1][3] += a1 * w.w;
            acc[2][0] += a2 * w.x; acc[2][1] += a2 * w.y; acc[2][2] += a2 * w.z; acc[2][3] += a2 * w.w;
            acc[3][0] += a3 * w.x; acc[3][1] += a3 * w.y; acc[3][2] += a3 * w.z; acc[3][3] += a3 * w.w;
        }
        __syncthreads();
    }

#pragma unroll
    for (int i = 0; i < 4; ++i) {
        int gr = brow + ty * 4 + i;
        if (gr >= M) continue;
#pragma unroll
        for (int j = 0; j < 4; ++j) {
            int gc = bcol + tx * 4 + j;
            float v = acc[i][j];
            if (MODE == 1) v += bias_ext[gc];
            if (MODE == 2) v = leakyf(v + g_B[gr * Kout + gc] + g_bsum[gc]);
            C[gr * Kout + gc] = v;
        }
    }
}

// ---------------- launch ----------------
extern "C" void kernel_launch(void* const* d_in, const int* in_sizes, int n_in,
                              void* d_out, int out_size) {
    const float* X     = (const float*)d_in[0];
    const int* eidx    = (const int*)d_in[1];   // int32 or int64 (auto-detected)
    const int* hidx    = (const int*)d_in[2];
    const float* hc1w  = (const float*)d_in[3];
    const float* hc1b  = (const float*)d_in[4];
    const float* lin1w = (const float*)d_in[5];
    const float* lin1b = (const float*)d_in[6];
    const float* hc2w  = (const float*)d_in[7];
    const float* hc2b  = (const float*)d_in[8];
    const float* lin2w = (const float*)d_in[9];
    const float* lin2b = (const float*)d_in[10];
    const float* c1wrel  = (const float*)d_in[11];
    const float* c1brel  = (const float*)d_in[12];
    const float* c1wroot = (const float*)d_in[13];
    const float* glin1w  = (const float*)d_in[14];
    const float* glin1b  = (const float*)d_in[15];
    const float* c2wrel  = (const float*)d_in[16];
    const float* c2brel  = (const float*)d_in[17];
    const float* c2wroot = (const float*)d_in[18];
    const float* glin2w  = (const float*)d_in[19];
    const float* glin2b  = (const float*)d_in[20];
    const float* fcw = (const float*)d_in[21];
    const float* fcb = (const float*)d_in[22];

    // out_size-adaptive output placement: expected layout is X (NN*HID) then y (NN*OUTC)
    const size_t NX = (size_t)NN * HID;
    const size_t NYsz = (size_t)NN * OUTC;
    bool full_out = ((size_t)out_size >= NX + NYsz);
    float* outX = (float*)d_out;               // valid only if full_out
    float* outY = full_out ? (outX + NX) : (float*)d_out;
    // final X gemm: write to d_out if full layout, else keep in g_X2 (csel=3)
    int final_csel = full_out ? -1 : 3;
    int fc_asel    = full_out ? -1 : 3;
    const float* fc_Aext = full_out ? outX : (const float*)0;  // only dereferenced when fc_asel == -1

    const int TPB = 256;
    dim3 g2(2, (NN + 63) / 64);   // Kout=128
    dim3 g1(1, (NN + 63) / 64);   // Kout=64
    int gbE   = (NE + TPB - 1) / TPB;
    int gbHEw = (NHE * 32 + TPB - 1) / TPB;   // warps over hyperedges
    int gbNw  = (NN * 32 + TPB - 1) / TPB;    // warps over nodes

    // ---- dtype detect + CSR build ----
    detect_kernel<<<1, 256>>>(hidx);
    zero_deg_kernel<<<(NN + TPB - 1) / TPB, TPB>>>();
    count_kernel<<<gbE, TPB>>>(hidx, eidx);
    scan_kernel<<<1, 1024>>>(0);
    scan_kernel<<<1, 1024>>>(1);
    scan_kernel<<<1, 1024>>>(2);
    fill_kernel<<<gbE, TPB>>>(hidx, eidx);

    // ---- layer 1 (hypergraph) ----
    gemm_kernel<0><<<g2, TPB>>>(X, hc1w, 0, 0, -1, 0, 0, NN, 128);   // g_A = X @ hc1w
    gemm_kernel<0><<<g2, TPB>>>(X, lin1w, 0, 0, -1, 1, 0, NN, 128);  // g_B = X @ lin1w
    gather_he_kernel<<<gbHEw, TPB>>>();
    gather_node_fuse_kernel<<<gbNw, TPB>>>((const float4*)hc1b, (const float4*)lin1b, 2);  // -> g_X1

    // ---- layer 2 (hypergraph) ----
    gemm_kernel<0><<<g2, TPB>>>(0, hc2w, 0, 0, 2, 0, 0, NN, 128);    // g_A = g_X1 @ hc2w
    gemm_kernel<0><<<g2, TPB>>>(0, lin2w, 0, 0, 2, 1, 0, NN, 128);   // g_B = g_X1 @ lin2w
    gather_he_kernel<<<gbHEw, TPB>>>();
    gather_node_fuse_kernel<<<gbNw, TPB>>>((const float4*)hc2b, (const float4*)lin2b, 3);  // -> g_X2

    // ---- layer 3 (graph) ----
    combine_kernel<<<(HID * HID + TPB - 1) / TPB, TPB>>>(c1wroot, glin1w, c1brel, glin1b);
    gather_edge_kernel<<<gbNw, TPB>>>(3);                            // g_A = segsum(g_X2)
    gemm_kernel<0><<<g2, TPB>>>(0, c1wrel, 0, 0, 0, 1, 0, NN, 128);  // g_B = g_A @ c1wrel
    gemm_kernel<2><<<g2, TPB>>>(0, 0, 0, 0, 3, 2, 1, NN, 128);       // g_X1 = leaky(g_X2@Wc + g_B + bsum)

    // ---- layer 4 (graph) ----
    combine_kernel<<<(HID * HID + TPB - 1) / TPB, TPB>>>(c2wroot, glin2w, c2brel, glin2b);
    gather_edge_kernel<<<gbNw, TPB>>>(2);                            // g_A = segsum(g_X1)
    gemm_kernel<0><<<g2, TPB>>>(0, c2wrel, 0, 0, 0, 1, 0, NN, 128);  // g_B = g_A @ c2wrel
    gemm_kernel<2><<<g2, TPB>>>(0, 0, outX, 0, 2, final_csel, 1, NN, 128);  // X4

    // ---- fc head ----
    gemm_kernel<1><<<g1, TPB>>>(fc_Aext, fcw, outY, fcb, fc_asel, -1, 0, NN, 64);
}